// round 11
// baseline (speedup 1.0000x reference)
#include <cuda_runtime.h>
#include <cuda_bf16.h>
#include <mma.h>
#include <math.h>
#include <stdint.h>

using namespace nvcuda;

#define NFEAT 128
#define HID   64
#define NCLS  40
#define MAXN  100000
#define MAXE  600000
#define SCAN_CHUNK 4096
#define PADW 136                      // padded smem row for gemm1 (bf16 elems)
#define PADA2 72                      // gemm2 A row pad (K=64)
#define PADB2 88                      // gemm2 B row pad (N=80)

// ---------------- scratch ----------------
__device__ float g_t1[(size_t)MAXN * 128];   // [x@W1l | x@W1r]
__device__ float g_t2[(size_t)MAXN * 80];    // [h@W2l | h@W2r]
__device__ __nv_bfloat16 g_hhi[(size_t)MAXN * 64];  // hidden, bf16 hi
__device__ __nv_bfloat16 g_hlo[(size_t)MAXN * 64];  // hidden, bf16 lo
__device__ __nv_bfloat16 g_w1hi[128 * 128];
__device__ __nv_bfloat16 g_w1lo[128 * 128];
__device__ __nv_bfloat16 g_w2hi[64 * 80];
__device__ __nv_bfloat16 g_w2lo[64 * 80];
__device__ int   g_deg[MAXN];
__device__ int   g_cur[MAXN];
__device__ int   g_rowptr[MAXN + 1];
__device__ int   g_adj[MAXE];
__device__ int   g_bsum[32];
__device__ int   g_bflag[32];

// ---------------- side stream + events (created once at load) -------
static cudaStream_t g_s2;
static cudaEvent_t  g_evFork, g_evG1;
static struct _StreamInit {
    _StreamInit() {
        cudaStreamCreateWithFlags(&g_s2, cudaStreamNonBlocking);
        cudaEventCreateWithFlags(&g_evFork, cudaEventDisableTiming);
        cudaEventCreateWithFlags(&g_evG1,   cudaEventDisableTiming);
    }
} g_streamInit;

// ---------------- bf16 split helper ----------------
__device__ __forceinline__ void split4(const float4& v, uint32_t* hi2, uint32_t* lo2) {
    uint32_t h01, h23;
    asm("cvt.rn.bf16x2.f32 %0, %1, %2;" : "=r"(h01) : "f"(v.y), "f"(v.x));
    asm("cvt.rn.bf16x2.f32 %0, %1, %2;" : "=r"(h23) : "f"(v.w), "f"(v.z));
    float l0 = v.x - __uint_as_float(h01 << 16);
    float l1 = v.y - __uint_as_float(h01 & 0xffff0000u);
    float l2 = v.z - __uint_as_float(h23 << 16);
    float l3 = v.w - __uint_as_float(h23 & 0xffff0000u);
    asm("cvt.rn.bf16x2.f32 %0, %1, %2;" : "=r"(lo2[0]) : "f"(l1), "f"(l0));
    asm("cvt.rn.bf16x2.f32 %0, %1, %2;" : "=r"(lo2[1]) : "f"(l3), "f"(l2));
    hi2[0] = h01; hi2[1] = h23;
}

// ---------------- per-block inline dtype detect ----------------
__device__ __forceinline__ int detect_is64(const void* ei, int E, int N,
                                           int tid, int* s_flag) {
    if (tid < 32) {
        int samples = (E < 32) ? E : 32;
        bool bad = false;
        if (tid < samples) {
            long long v = ((const long long*)ei)[tid];
            bad = (v < 0 || v >= (long long)N);
        }
        unsigned m = __ballot_sync(0xffffffffu, bad);
        if (tid == 0) *s_flag = (m == 0u) ? 1 : 0;
    }
    __syncthreads();
    return *s_flag;
}

__device__ __forceinline__ int load_idx2(const void* ei, int pos, int is64) {
    if (is64) return (int)((const long long*)ei)[pos];
    return ((const int*)ei)[pos];
}

// ---------------- combined W split: W1 -> g_w1*, W2 -> g_w2* ----------
__global__ void k_wsplit_all(const float* __restrict__ W1l, const float* __restrict__ W1r,
                             const float* __restrict__ W2l, const float* __restrict__ W2r) {
    int p = blockIdx.x * blockDim.x + threadIdx.x;
    if (p < 4096) {                                    // W1: 4096 float4 slots
        int k = p >> 5, cq = p & 31;
        const float* src = (cq < 16) ? (W1l + k * 64 + cq * 4)
                                     : (W1r + k * 64 + (cq - 16) * 4);
        float4 v = *(const float4*)src;
        uint32_t hi2[2], lo2[2];
        split4(v, hi2, lo2);
        ((uint32_t*)(g_w1hi + k * 128 + cq * 4))[0] = hi2[0];
        ((uint32_t*)(g_w1hi + k * 128 + cq * 4))[1] = hi2[1];
        ((uint32_t*)(g_w1lo + k * 128 + cq * 4))[0] = lo2[0];
        ((uint32_t*)(g_w1lo + k * 128 + cq * 4))[1] = lo2[1];
    } else if (p < 4096 + 1280) {                      // W2: 1280 float4 slots
        int q = p - 4096;
        int k = q / 20, cq = q % 20;
        const float* src = (cq < 10) ? (W2l + k * 40 + cq * 4)
                                     : (W2r + k * 40 + (cq - 10) * 4);
        float4 v = *(const float4*)src;
        uint32_t hi2[2], lo2[2];
        split4(v, hi2, lo2);
        ((uint32_t*)(g_w2hi + k * 80 + cq * 4))[0] = hi2[0];
        ((uint32_t*)(g_w2hi + k * 80 + cq * 4))[1] = hi2[1];
        ((uint32_t*)(g_w2lo + k * 80 + cq * 4))[0] = lo2[0];
        ((uint32_t*)(g_w2lo + k * 80 + cq * 4))[1] = lo2[1];
    }
}

// g_deg is zero here (module load / re-zeroed by k_scan every call)
__global__ void k_hist(const void* __restrict__ ei, int E, int N) {
    __shared__ int s_flag;
    int is64 = detect_is64(ei, E, N, threadIdx.x, &s_flag);
    int half = (E + 1) >> 1;
    int e = blockIdx.x * blockDim.x + threadIdx.x;
    int d0 = -1, d1 = -1;
    if (e < half)        d0 = min(max(load_idx2(ei, E + e, is64), 0), N - 1);
    if (e + half < E)    d1 = min(max(load_idx2(ei, E + e + half, is64), 0), N - 1);
    if (d0 >= 0) atomicAdd(&g_deg[d0], 1);
    if (d1 >= 0) atomicAdd(&g_deg[d1], 1);
}

// ---- single-pass scan with decoupled block-sum lookback ----
__global__ void k_scan(int n) {
    const int tid = threadIdx.x, lane = tid & 31, wid = tid >> 5;
    const int bid = blockIdx.x;
    __shared__ int wsum[32];
    __shared__ int s_off;
    int idx = bid * SCAN_CHUNK + tid * 4;
    int v0 = 0, v1 = 0, v2 = 0, v3 = 0;
    if (idx + 0 < n) { v0 = g_deg[idx + 0]; g_deg[idx + 0] = 0; }
    if (idx + 1 < n) { v1 = g_deg[idx + 1]; g_deg[idx + 1] = 0; }
    if (idx + 2 < n) { v2 = g_deg[idx + 2]; g_deg[idx + 2] = 0; }
    if (idx + 3 < n) { v3 = g_deg[idx + 3]; g_deg[idx + 3] = 0; }
    int s = v0 + v1 + v2 + v3;
    int sc = s;
    #pragma unroll
    for (int d = 1; d < 32; d <<= 1) {
        int t = __shfl_up_sync(0xffffffffu, sc, d);
        if (lane >= d) sc += t;
    }
    if (lane == 31) wsum[wid] = sc;
    __syncthreads();
    if (wid == 0) {
        int ws = wsum[lane];
        #pragma unroll
        for (int d = 1; d < 32; d <<= 1) {
            int t = __shfl_up_sync(0xffffffffu, ws, d);
            if (lane >= d) ws += t;
        }
        wsum[lane] = ws;
    }
    __syncthreads();
    int warp_excl = (wid == 0) ? 0 : wsum[wid - 1];
    int excl = warp_excl + (sc - s);

    if (tid == 1023) {
        g_bsum[bid] = warp_excl + sc;
        __threadfence();
        atomicExch(&g_bflag[bid], 1);
    }
    if (tid < 32) {
        int acc = 0;
        for (int j = lane; j < bid; j += 32) {
            while (atomicAdd(&g_bflag[j], 0) == 0) {}
            acc += atomicAdd(&g_bsum[j], 0);
        }
        #pragma unroll
        for (int d = 16; d > 0; d >>= 1)
            acc += __shfl_down_sync(0xffffffffu, acc, d);
        if (lane == 0) s_off = acc;
    }
    __syncthreads();
    int off = s_off + excl;
    int p0 = off + v0, p1 = p0 + v1, p2 = p1 + v2, p3 = p2 + v3;
    if (idx + 0 < n) g_rowptr[idx + 1] = p0;
    if (idx + 1 < n) g_rowptr[idx + 2] = p1;
    if (idx + 2 < n) g_rowptr[idx + 3] = p2;
    if (idx + 3 < n) g_rowptr[idx + 4] = p3;
    if (bid == 0 && tid == 0) g_rowptr[0] = 0;
}

// g_cur is zero here (module load / reset by final k_finish)
__global__ void k_fill(const void* __restrict__ ei, int E, int N) {
    __shared__ int s_flag;
    int is64 = detect_is64(ei, E, N, threadIdx.x, &s_flag);
    if (blockIdx.x == 0 && threadIdx.x < 32) g_bflag[threadIdx.x] = 0;
    int half = (E + 1) >> 1;
    int e = blockIdx.x * blockDim.x + threadIdx.x;
    if (e < half) {
        int dst = min(max(load_idx2(ei, E + e, is64), 0), N - 1);
        int src = min(max(load_idx2(ei, e, is64), 0), N - 1);
        int pos = g_rowptr[dst] + atomicAdd(&g_cur[dst], 1);
        if (pos < E) g_adj[pos] = src;
    }
    if (e + half < E) {
        int dst = min(max(load_idx2(ei, E + e + half, is64), 0), N - 1);
        int src = min(max(load_idx2(ei, e + half, is64), 0), N - 1);
        int pos = g_rowptr[dst] + atomicAdd(&g_cur[dst], 1);
        if (pos < E) g_adj[pos] = src;
    }
}

// ---------------- GEMM1 via WMMA bf16 split: T1 = X @ [W1l|W1r] ----------
#define GEMM1_SMEM ((2 * 128 + 2 * 64) * PADW * 2)

__global__ void __launch_bounds__(256, 2)
k_gemm1_wmma(const float* __restrict__ X, float* __restrict__ T, int n) {
    extern __shared__ char smraw[];
    __nv_bfloat16* Whi = (__nv_bfloat16*)smraw;          // [128][PADW]
    __nv_bfloat16* Wlo = Whi + 128 * PADW;
    __nv_bfloat16* Ahi = Wlo + 128 * PADW;               // [64][PADW]
    __nv_bfloat16* Alo = Ahi + 64 * PADW;
    const int tid = threadIdx.x, wid = tid >> 5;
    const int row0 = blockIdx.x * 64;

    #pragma unroll
    for (int it = 0; it < 8; it++) {
        int p = it * 256 + tid;
        int k = p >> 4, c = p & 15;
        *(uint4*)(Whi + k * PADW + c * 8) = ((const uint4*)g_w1hi)[p];
        *(uint4*)(Wlo + k * PADW + c * 8) = ((const uint4*)g_w1lo)[p];
    }
    #pragma unroll
    for (int it = 0; it < 8; it++) {
        int p = it * 256 + tid;
        int r = p >> 5, cq = p & 31;
        float4 v = make_float4(0.f, 0.f, 0.f, 0.f);
        if (row0 + r < n) v = ((const float4*)(X + (size_t)(row0 + r) * 128))[cq];
        uint32_t hi2[2], lo2[2];
        split4(v, hi2, lo2);
        uint32_t* ah = (uint32_t*)(Ahi + r * PADW + cq * 4);
        uint32_t* al = (uint32_t*)(Alo + r * PADW + cq * 4);
        ah[0] = hi2[0]; ah[1] = hi2[1];
        al[0] = lo2[0]; al[1] = lo2[1];
    }
    __syncthreads();

    const int m0 = (wid & 1) * 32;
    const int n0 = (wid >> 1) * 32;

    wmma::fragment<wmma::accumulator, 16, 16, 16, float> acc[2][2];
    #pragma unroll
    for (int r = 0; r < 2; r++)
        #pragma unroll
        for (int c = 0; c < 2; c++) wmma::fill_fragment(acc[r][c], 0.f);

    const __nv_bfloat16* Ap[3] = {Ahi, Ahi, Alo};
    const __nv_bfloat16* Bp[3] = {Whi, Wlo, Whi};

    #pragma unroll
    for (int pass = 0; pass < 3; pass++) {
        const __nv_bfloat16* A = Ap[pass];
        const __nv_bfloat16* B = Bp[pass];
        #pragma unroll
        for (int k = 0; k < 128; k += 16) {
            wmma::fragment<wmma::matrix_a, 16, 16, 16, __nv_bfloat16, wmma::row_major> a[2];
            wmma::load_matrix_sync(a[0], A + (m0 + 0)  * PADW + k, PADW);
            wmma::load_matrix_sync(a[1], A + (m0 + 16) * PADW + k, PADW);
            wmma::fragment<wmma::matrix_b, 16, 16, 16, __nv_bfloat16, wmma::row_major> b[2];
            wmma::load_matrix_sync(b[0], B + k * PADW + n0,      PADW);
            wmma::load_matrix_sync(b[1], B + k * PADW + n0 + 16, PADW);
            #pragma unroll
            for (int r = 0; r < 2; r++)
                #pragma unroll
                for (int c = 0; c < 2; c++)
                    wmma::mma_sync(acc[r][c], a[r], b[c], acc[r][c]);
        }
    }

    __syncthreads();
    float* stage = (float*)smraw;        // [64][128]
    #pragma unroll
    for (int r = 0; r < 2; r++)
        #pragma unroll
        for (int c = 0; c < 2; c++)
            wmma::store_matrix_sync(stage + (m0 + r * 16) * 128 + n0 + c * 16,
                                    acc[r][c], 128, wmma::mem_row_major);
    __syncthreads();
    #pragma unroll
    for (int it = 0; it < 8; it++) {
        int p = it * 256 + tid;
        int r = p >> 5, cq = p & 31;
        if (row0 + r < n)
            ((float4*)(T + (size_t)(row0 + r) * 128))[cq] = ((float4*)(stage + r * 128))[cq];
    }
}

// -------- finish layer1: gather t1 + mean + bias + sigmoid -> h (bf16 hi/lo) ----
__global__ void k_finish1(const float* __restrict__ T, const float* __restrict__ bias,
                          int n) {
    int gid = blockIdx.x * blockDim.x + threadIdx.x;     // node*16 + q
    int node = gid >> 4;
    int q = gid & 15;
    if (node >= n) return;
    int s = g_rowptr[node], e = g_rowptr[node + 1];
    float4 a0 = make_float4(0.f, 0.f, 0.f, 0.f);
    float4 a1 = make_float4(0.f, 0.f, 0.f, 0.f);
    float4 a2 = make_float4(0.f, 0.f, 0.f, 0.f);
    float4 a3 = make_float4(0.f, 0.f, 0.f, 0.f);
    int p = s;
    for (; p + 3 < e; p += 4) {
        int j0 = g_adj[p], j1 = g_adj[p + 1], j2 = g_adj[p + 2], j3 = g_adj[p + 3];
        float4 v0 = *(const float4*)(T + (size_t)j0 * 128 + q * 4);
        float4 v1 = *(const float4*)(T + (size_t)j1 * 128 + q * 4);
        float4 v2 = *(const float4*)(T + (size_t)j2 * 128 + q * 4);
        float4 v3 = *(const float4*)(T + (size_t)j3 * 128 + q * 4);
        a0.x += v0.x; a0.y += v0.y; a0.z += v0.z; a0.w += v0.w;
        a1.x += v1.x; a1.y += v1.y; a1.z += v1.z; a1.w += v1.w;
        a2.x += v2.x; a2.y += v2.y; a2.z += v2.z; a2.w += v2.w;
        a3.x += v3.x; a3.y += v3.y; a3.z += v3.z; a3.w += v3.w;
    }
    for (; p < e; p++) {
        int j = g_adj[p];
        float4 v = *(const float4*)(T + (size_t)j * 128 + q * 4);
        a0.x += v.x; a0.y += v.y; a0.z += v.z; a0.w += v.w;
    }
    a0.x += a1.x + a2.x + a3.x;
    a0.y += a1.y + a2.y + a3.y;
    a0.z += a1.z + a2.z + a3.z;
    a0.w += a1.w + a2.w + a3.w;
    float inv = 1.f / fmaxf((float)(e - s), 1.f);
    float4 r = *(const float4*)(T + (size_t)node * 128 + 64 + q * 4);
    float4 b = *(const float4*)(bias + q * 4);
    float4 o;
    o.x = fmaf(a0.x, inv, r.x + b.x);
    o.y = fmaf(a0.y, inv, r.y + b.y);
    o.z = fmaf(a0.z, inv, r.z + b.z);
    o.w = fmaf(a0.w, inv, r.w + b.w);
    o.x = 1.f / (1.f + expf(-o.x));
    o.y = 1.f / (1.f + expf(-o.y));
    o.z = 1.f / (1.f + expf(-o.z));
    o.w = 1.f / (1.f + expf(-o.w));
    uint32_t hi2[2], lo2[2];
    split4(o, hi2, lo2);
    *(uint2*)(g_hhi + (size_t)node * 64 + q * 4) = make_uint2(hi2[0], hi2[1]);
    *(uint2*)(g_hlo + (size_t)node * 64 + q * 4) = make_uint2(lo2[0], lo2[1]);
}

// ---------------- GEMM2 via WMMA bf16 split: T2 = H @ [W2l|W2r] ----------------
#define GEMM2_SMEM ((2 * 64 * PADB2 + 2 * 128 * PADA2) * 2)

__global__ void __launch_bounds__(320, 2)
k_gemm2_wmma(float* __restrict__ T, int n) {
    extern __shared__ char smraw[];
    __nv_bfloat16* Whi = (__nv_bfloat16*)smraw;           // [64][PADB2]
    __nv_bfloat16* Wlo = Whi + 64 * PADB2;
    __nv_bfloat16* Ahi = Wlo + 64 * PADB2;                // [128][PADA2]
    __nv_bfloat16* Alo = Ahi + 128 * PADA2;
    const int tid = threadIdx.x, wid = tid >> 5;
    const int row0 = blockIdx.x * 128;

    for (int p = tid; p < 640; p += 320) {
        int k = p / 10, c = p % 10;
        *(uint4*)(Whi + k * PADB2 + c * 8) = ((const uint4*)g_w2hi)[p];
        *(uint4*)(Wlo + k * PADB2 + c * 8) = ((const uint4*)g_w2lo)[p];
    }
    // H tile pre-split: direct uint2 copies (no conversion)
    for (int p = tid; p < 2048; p += 320) {
        int r = p >> 4, cq = p & 15;
        uint2 hv = make_uint2(0u, 0u), lv = make_uint2(0u, 0u);
        if (row0 + r < n) {
            hv = *(const uint2*)(g_hhi + (size_t)(row0 + r) * 64 + cq * 4);
            lv = *(const uint2*)(g_hlo + (size_t)(row0 + r) * 64 + cq * 4);
        }
        *(uint2*)(Ahi + r * PADA2 + cq * 4) = hv;
        *(uint2*)(Alo + r * PADA2 + cq * 4) = lv;
    }
    __syncthreads();

    const int n0 = (wid % 5) * 16;
    const int m0 = (wid / 5) * 64;

    wmma::fragment<wmma::accumulator, 16, 16, 16, float> acc[4];
    #pragma unroll
    for (int r = 0; r < 4; r++) wmma::fill_fragment(acc[r], 0.f);

    const __nv_bfloat16* Ap[3] = {Ahi, Ahi, Alo};
    const __nv_bfloat16* Bp[3] = {Whi, Wlo, Whi};

    #pragma unroll
    for (int pass = 0; pass < 3; pass++) {
        const __nv_bfloat16* A = Ap[pass];
        const __nv_bfloat16* B = Bp[pass];
        #pragma unroll
        for (int k = 0; k < 64; k += 16) {
            wmma::fragment<wmma::matrix_b, 16, 16, 16, __nv_bfloat16, wmma::row_major> b;
            wmma::load_matrix_sync(b, B + k * PADB2 + n0, PADB2);
            #pragma unroll
            for (int r = 0; r < 4; r++) {
                wmma::fragment<wmma::matrix_a, 16, 16, 16, __nv_bfloat16, wmma::row_major> a;
                wmma::load_matrix_sync(a, A + (m0 + r * 16) * PADA2 + k, PADA2);
                wmma::mma_sync(acc[r], a, b, acc[r]);
            }
        }
    }

    __syncthreads();
    float* stage = (float*)smraw;        // [128][80]
    #pragma unroll
    for (int r = 0; r < 4; r++)
        wmma::store_matrix_sync(stage + (m0 + r * 16) * 80 + n0, acc[r], 80,
                                wmma::mem_row_major);
    __syncthreads();
    for (int p = tid; p < 2560; p += 320) {
        int r = p / 20, cq = p % 20;
        if (row0 + r < n)
            ((float4*)(T + (size_t)(row0 + r) * 80))[cq] = ((float4*)(stage + r * 80))[cq];
    }
}

// -------- final: aggregate t2 + mean + residual + bias --------
__global__ void k_finish2(const float* __restrict__ T, const float* __restrict__ bias,
                          float* __restrict__ out, int n) {
    constexpr int Q = 10;
    int gid = blockIdx.x * blockDim.x + threadIdx.x;
    int node = gid / Q;
    int q = gid - node * Q;
    if (node >= n) return;
    int s = g_rowptr[node], e = g_rowptr[node + 1];
    float4 a0 = make_float4(0.f, 0.f, 0.f, 0.f);
    float4 a1 = make_float4(0.f, 0.f, 0.f, 0.f);
    int p = s;
    for (; p + 1 < e; p += 2) {
        int j0 = g_adj[p], j1 = g_adj[p + 1];
        float4 v0 = *(const float4*)(T + (size_t)j0 * 80 + q * 4);
        float4 v1 = *(const float4*)(T + (size_t)j1 * 80 + q * 4);
        a0.x += v0.x; a0.y += v0.y; a0.z += v0.z; a0.w += v0.w;
        a1.x += v1.x; a1.y += v1.y; a1.z += v1.z; a1.w += v1.w;
    }
    if (p < e) {
        int j = g_adj[p];
        float4 v = *(const float4*)(T + (size_t)j * 80 + q * 4);
        a0.x += v.x; a0.y += v.y; a0.z += v.z; a0.w += v.w;
    }
    a0.x += a1.x; a0.y += a1.y; a0.z += a1.z; a0.w += a1.w;
    float inv = 1.f / fmaxf((float)(e - s), 1.f);
    float4 r = *(const float4*)(T + (size_t)node * 80 + 40 + q * 4);
    float4 b = *(const float4*)(bias + q * 4);
    float4 o;
    o.x = fmaf(a0.x, inv, r.x + b.x);
    o.y = fmaf(a0.y, inv, r.y + b.y);
    o.z = fmaf(a0.z, inv, r.z + b.z);
    o.w = fmaf(a0.w, inv, r.w + b.w);
    *(float4*)(out + (size_t)node * 40 + q * 4) = o;
    if (q == 0) g_cur[node] = 0;   // reset for next call
}

// ---------------- launch ----------------
extern "C" void kernel_launch(void* const* d_in, const int* in_sizes, int n_in,
                              void* d_out, int out_size) {
    const float* x   = (const float*)d_in[0];
    const void*  ei  = d_in[1];
    const float* W1l = (const float*)d_in[2];
    const float* b1  = (const float*)d_in[3];
    const float* W1r = (const float*)d_in[4];
    const float* W2l = (const float*)d_in[5];
    const float* b2  = (const float*)d_in[6];
    const float* W2r = (const float*)d_in[7];
    float* out = (float*)d_out;

    const int N = in_sizes[0] / NFEAT;
    const int E = in_sizes[1] / 2;
    const int NB = (N + SCAN_CHUNK - 1) / SCAN_CHUNK;
    const int EH = ((E + 1) / 2 + 255) / 256;

    void *t1p, *t2p;
    cudaGetSymbolAddress(&t1p, g_t1);
    cudaGetSymbolAddress(&t2p, g_t2);

    cudaFuncSetAttribute(k_gemm1_wmma, cudaFuncAttributeMaxDynamicSharedMemorySize, GEMM1_SMEM);
    cudaFuncSetAttribute(k_gemm2_wmma, cudaFuncAttributeMaxDynamicSharedMemorySize, GEMM2_SMEM);

    // fork: side stream = weights + GEMM1; main stream = graph build
    cudaEventRecord(g_evFork, 0);
    cudaStreamWaitEvent(g_s2, g_evFork, 0);

    k_wsplit_all<<<21, 256, 0, g_s2>>>(W1l, W1r, W2l, W2r);          // #1
    k_hist<<<EH, 256>>>(ei, E, N);                                   // #2
    k_scan<<<NB, 1024>>>(N);                                         // #3
    k_gemm1_wmma<<<(N + 63) / 64, 256, GEMM1_SMEM, g_s2>>>(x, (float*)t1p, N);  // #4
    k_fill<<<EH, 256>>>(ei, E, N);                                   // #5

    // join
    cudaEventRecord(g_evG1, g_s2);
    cudaStreamWaitEvent(0, g_evG1, 0);

    // tail (full-range, single stream: these kernels fill the chip)
    int tot1 = N * 16;
    k_finish1<<<(tot1 + 255) / 256, 256>>>((const float*)t1p, b1, N);          // #6
    k_gemm2_wmma<<<(N + 127) / 128, 320, GEMM2_SMEM>>>((float*)t2p, N);        // #7
    int tot2 = N * 10;
    k_finish2<<<(tot2 + 255) / 256, 256>>>((const float*)t2p, b2, out, N);     // #8
}

// round 12
// speedup vs baseline: 1.2368x; 1.2368x over previous
#include <cuda_runtime.h>
#include <cuda_bf16.h>
#include <mma.h>
#include <math.h>
#include <stdint.h>

using namespace nvcuda;

#define NFEAT 128
#define HID   64
#define NCLS  40
#define MAXN  100000
#define MAXE  600000
#define SCAN_CHUNK 4096
#define PADW 136                      // gemm1 smem row pad (bf16 elems)
#define PADA2 72                      // gemm2 A row pad (K=64)
#define PADB2 88                      // gemm2 B row pad (N=80)

// ---------------- scratch (padded by one tile for unguarded frag stores) -----
__device__ float g_t1[(size_t)(MAXN + 64) * 128];
__device__ float g_t2[(size_t)(MAXN + 128) * 80];
__device__ __nv_bfloat16 g_hhi[(size_t)MAXN * 64];
__device__ __nv_bfloat16 g_hlo[(size_t)MAXN * 64];
__device__ __nv_bfloat16 g_w1hi[128 * 128];
__device__ __nv_bfloat16 g_w1lo[128 * 128];
__device__ __nv_bfloat16 g_w2hi[64 * 80];
__device__ __nv_bfloat16 g_w2lo[64 * 80];
__device__ int   g_deg[MAXN];
__device__ int   g_cur[MAXN];
__device__ int   g_rowptr[MAXN + 1];
__device__ int   g_adj[MAXE];
__device__ int   g_bsum[32];
__device__ int   g_bflag[32];

// ---------------- side stream + events (created once at load) -------
static cudaStream_t g_s2;
static cudaEvent_t  g_evFork, g_evG1;
static struct _StreamInit {
    _StreamInit() {
        cudaStreamCreateWithFlags(&g_s2, cudaStreamNonBlocking);
        cudaEventCreateWithFlags(&g_evFork, cudaEventDisableTiming);
        cudaEventCreateWithFlags(&g_evG1,   cudaEventDisableTiming);
    }
} g_streamInit;

// ---------------- bf16 split helper ----------------
__device__ __forceinline__ void split4(const float4& v, uint32_t* hi2, uint32_t* lo2) {
    uint32_t h01, h23;
    asm("cvt.rn.bf16x2.f32 %0, %1, %2;" : "=r"(h01) : "f"(v.y), "f"(v.x));
    asm("cvt.rn.bf16x2.f32 %0, %1, %2;" : "=r"(h23) : "f"(v.w), "f"(v.z));
    float l0 = v.x - __uint_as_float(h01 << 16);
    float l1 = v.y - __uint_as_float(h01 & 0xffff0000u);
    float l2 = v.z - __uint_as_float(h23 << 16);
    float l3 = v.w - __uint_as_float(h23 & 0xffff0000u);
    asm("cvt.rn.bf16x2.f32 %0, %1, %2;" : "=r"(lo2[0]) : "f"(l1), "f"(l0));
    asm("cvt.rn.bf16x2.f32 %0, %1, %2;" : "=r"(lo2[1]) : "f"(l3), "f"(l2));
    hi2[0] = h01; hi2[1] = h23;
}

// ---------------- per-block inline dtype detect ----------------
__device__ __forceinline__ int detect_is64(const void* ei, int E, int N,
                                           int tid, int* s_flag) {
    if (tid < 32) {
        int samples = (E < 32) ? E : 32;
        bool bad = false;
        if (tid < samples) {
            long long v = ((const long long*)ei)[tid];
            bad = (v < 0 || v >= (long long)N);
        }
        unsigned m = __ballot_sync(0xffffffffu, bad);
        if (tid == 0) *s_flag = (m == 0u) ? 1 : 0;
    }
    __syncthreads();
    return *s_flag;
}

__device__ __forceinline__ int load_idx2(const void* ei, int pos, int is64) {
    if (is64) return (int)((const long long*)ei)[pos];
    return ((const int*)ei)[pos];
}

// ---------------- combined W split: W1 -> g_w1*, W2 -> g_w2* ----------
__global__ void k_wsplit_all(const float* __restrict__ W1l, const float* __restrict__ W1r,
                             const float* __restrict__ W2l, const float* __restrict__ W2r) {
    int p = blockIdx.x * blockDim.x + threadIdx.x;
    if (p < 4096) {
        int k = p >> 5, cq = p & 31;
        const float* src = (cq < 16) ? (W1l + k * 64 + cq * 4)
                                     : (W1r + k * 64 + (cq - 16) * 4);
        float4 v = *(const float4*)src;
        uint32_t hi2[2], lo2[2];
        split4(v, hi2, lo2);
        ((uint32_t*)(g_w1hi + k * 128 + cq * 4))[0] = hi2[0];
        ((uint32_t*)(g_w1hi + k * 128 + cq * 4))[1] = hi2[1];
        ((uint32_t*)(g_w1lo + k * 128 + cq * 4))[0] = lo2[0];
        ((uint32_t*)(g_w1lo + k * 128 + cq * 4))[1] = lo2[1];
    } else if (p < 4096 + 1280) {
        int q = p - 4096;
        int k = q / 20, cq = q % 20;
        const float* src = (cq < 10) ? (W2l + k * 40 + cq * 4)
                                     : (W2r + k * 40 + (cq - 10) * 4);
        float4 v = *(const float4*)src;
        uint32_t hi2[2], lo2[2];
        split4(v, hi2, lo2);
        ((uint32_t*)(g_w2hi + k * 80 + cq * 4))[0] = hi2[0];
        ((uint32_t*)(g_w2hi + k * 80 + cq * 4))[1] = hi2[1];
        ((uint32_t*)(g_w2lo + k * 80 + cq * 4))[0] = lo2[0];
        ((uint32_t*)(g_w2lo + k * 80 + cq * 4))[1] = lo2[1];
    }
}

// g_deg is zero here (module load / re-zeroed by k_scan every call)
__global__ void k_hist(const void* __restrict__ ei, int E, int N) {
    __shared__ int s_flag;
    int is64 = detect_is64(ei, E, N, threadIdx.x, &s_flag);
    int half = (E + 1) >> 1;
    int e = blockIdx.x * blockDim.x + threadIdx.x;
    int d0 = -1, d1 = -1;
    if (e < half)        d0 = min(max(load_idx2(ei, E + e, is64), 0), N - 1);
    if (e + half < E)    d1 = min(max(load_idx2(ei, E + e + half, is64), 0), N - 1);
    if (d0 >= 0) atomicAdd(&g_deg[d0], 1);
    if (d1 >= 0) atomicAdd(&g_deg[d1], 1);
}

// ---- single-pass scan with decoupled block-sum lookback ----
__global__ void k_scan(int n) {
    const int tid = threadIdx.x, lane = tid & 31, wid = tid >> 5;
    const int bid = blockIdx.x;
    __shared__ int wsum[32];
    __shared__ int s_off;
    int idx = bid * SCAN_CHUNK + tid * 4;
    int v0 = 0, v1 = 0, v2 = 0, v3 = 0;
    if (idx + 0 < n) { v0 = g_deg[idx + 0]; g_deg[idx + 0] = 0; }
    if (idx + 1 < n) { v1 = g_deg[idx + 1]; g_deg[idx + 1] = 0; }
    if (idx + 2 < n) { v2 = g_deg[idx + 2]; g_deg[idx + 2] = 0; }
    if (idx + 3 < n) { v3 = g_deg[idx + 3]; g_deg[idx + 3] = 0; }
    int s = v0 + v1 + v2 + v3;
    int sc = s;
    #pragma unroll
    for (int d = 1; d < 32; d <<= 1) {
        int t = __shfl_up_sync(0xffffffffu, sc, d);
        if (lane >= d) sc += t;
    }
    if (lane == 31) wsum[wid] = sc;
    __syncthreads();
    if (wid == 0) {
        int ws = wsum[lane];
        #pragma unroll
        for (int d = 1; d < 32; d <<= 1) {
            int t = __shfl_up_sync(0xffffffffu, ws, d);
            if (lane >= d) ws += t;
        }
        wsum[lane] = ws;
    }
    __syncthreads();
    int warp_excl = (wid == 0) ? 0 : wsum[wid - 1];
    int excl = warp_excl + (sc - s);

    if (tid == 1023) {
        g_bsum[bid] = warp_excl + sc;
        __threadfence();
        atomicExch(&g_bflag[bid], 1);
    }
    if (tid < 32) {
        int acc = 0;
        for (int j = lane; j < bid; j += 32) {
            while (atomicAdd(&g_bflag[j], 0) == 0) {}
            acc += atomicAdd(&g_bsum[j], 0);
        }
        #pragma unroll
        for (int d = 16; d > 0; d >>= 1)
            acc += __shfl_down_sync(0xffffffffu, acc, d);
        if (lane == 0) s_off = acc;
    }
    __syncthreads();
    int off = s_off + excl;
    int p0 = off + v0, p1 = p0 + v1, p2 = p1 + v2, p3 = p2 + v3;
    if (idx + 0 < n) g_rowptr[idx + 1] = p0;
    if (idx + 1 < n) g_rowptr[idx + 2] = p1;
    if (idx + 2 < n) g_rowptr[idx + 3] = p2;
    if (idx + 3 < n) g_rowptr[idx + 4] = p3;
    if (bid == 0 && tid == 0) g_rowptr[0] = 0;
}

// g_cur is zero here (module load / reset by final k_finish2)
__global__ void k_fill(const void* __restrict__ ei, int E, int N) {
    __shared__ int s_flag;
    int is64 = detect_is64(ei, E, N, threadIdx.x, &s_flag);
    if (blockIdx.x == 0 && threadIdx.x < 32) g_bflag[threadIdx.x] = 0;
    int half = (E + 1) >> 1;
    int e = blockIdx.x * blockDim.x + threadIdx.x;
    if (e < half) {
        int dst = min(max(load_idx2(ei, E + e, is64), 0), N - 1);
        int src = min(max(load_idx2(ei, e, is64), 0), N - 1);
        int pos = g_rowptr[dst] + atomicAdd(&g_cur[dst], 1);
        if (pos < E) g_adj[pos] = src;
    }
    if (e + half < E) {
        int dst = min(max(load_idx2(ei, E + e + half, is64), 0), N - 1);
        int src = min(max(load_idx2(ei, e + half, is64), 0), N - 1);
        int pos = g_rowptr[dst] + atomicAdd(&g_cur[dst], 1);
        if (pos < E) g_adj[pos] = src;
    }
}

// ------------- GEMM1, persistent: T1 = X @ [W1l|W1r] (bf16 3-pass split) -----
// W hi/lo resident in smem (loaded once per CTA); 64-row tiles strided over grid.
// Direct unguarded frag stores (g_t1 padded by 64 rows).
#define GEMM1_SMEM ((2 * 128 + 2 * 64) * PADW * 2)

__global__ void __launch_bounds__(256, 2)
k_gemm1_wmma(const float* __restrict__ X, float* __restrict__ T, int n) {
    extern __shared__ char smraw[];
    __nv_bfloat16* Whi = (__nv_bfloat16*)smraw;          // [128][PADW]
    __nv_bfloat16* Wlo = Whi + 128 * PADW;
    __nv_bfloat16* Ahi = Wlo + 128 * PADW;               // [64][PADW]
    __nv_bfloat16* Alo = Ahi + 64 * PADW;
    const int tid = threadIdx.x, wid = tid >> 5;

    // W resident: load once per CTA
    #pragma unroll
    for (int it = 0; it < 8; it++) {
        int p = it * 256 + tid;
        int k = p >> 4, c = p & 15;
        *(uint4*)(Whi + k * PADW + c * 8) = ((const uint4*)g_w1hi)[p];
        *(uint4*)(Wlo + k * PADW + c * 8) = ((const uint4*)g_w1lo)[p];
    }

    const int m0 = (wid & 1) * 32;
    const int n0 = (wid >> 1) * 32;
    const int ntiles = (n + 63) >> 6;

    for (int t = blockIdx.x; t < ntiles; t += gridDim.x) {
        const int row0 = t << 6;
        __syncthreads();               // prev tile's readers done (also orders W)
        #pragma unroll
        for (int it = 0; it < 8; it++) {
            int p = it * 256 + tid;
            int r = p >> 5, cq = p & 31;
            float4 v = make_float4(0.f, 0.f, 0.f, 0.f);
            if (row0 + r < n) v = ((const float4*)(X + (size_t)(row0 + r) * 128))[cq];
            uint32_t hi2[2], lo2[2];
            split4(v, hi2, lo2);
            uint32_t* ah = (uint32_t*)(Ahi + r * PADW + cq * 4);
            uint32_t* al = (uint32_t*)(Alo + r * PADW + cq * 4);
            ah[0] = hi2[0]; ah[1] = hi2[1];
            al[0] = lo2[0]; al[1] = lo2[1];
        }
        __syncthreads();

        wmma::fragment<wmma::accumulator, 16, 16, 16, float> acc[2][2];
        #pragma unroll
        for (int r = 0; r < 2; r++)
            #pragma unroll
            for (int c = 0; c < 2; c++) wmma::fill_fragment(acc[r][c], 0.f);

        #pragma unroll
        for (int k = 0; k < 128; k += 16) {
            wmma::fragment<wmma::matrix_a, 16, 16, 16, __nv_bfloat16, wmma::row_major> ah[2], al[2];
            wmma::load_matrix_sync(ah[0], Ahi + (m0 + 0)  * PADW + k, PADW);
            wmma::load_matrix_sync(ah[1], Ahi + (m0 + 16) * PADW + k, PADW);
            wmma::load_matrix_sync(al[0], Alo + (m0 + 0)  * PADW + k, PADW);
            wmma::load_matrix_sync(al[1], Alo + (m0 + 16) * PADW + k, PADW);
            wmma::fragment<wmma::matrix_b, 16, 16, 16, __nv_bfloat16, wmma::row_major> bh[2], bl[2];
            wmma::load_matrix_sync(bh[0], Whi + k * PADW + n0,      PADW);
            wmma::load_matrix_sync(bh[1], Whi + k * PADW + n0 + 16, PADW);
            wmma::load_matrix_sync(bl[0], Wlo + k * PADW + n0,      PADW);
            wmma::load_matrix_sync(bl[1], Wlo + k * PADW + n0 + 16, PADW);
            #pragma unroll
            for (int r = 0; r < 2; r++)
                #pragma unroll
                for (int c = 0; c < 2; c++) {
                    wmma::mma_sync(acc[r][c], ah[r], bh[c], acc[r][c]);
                    wmma::mma_sync(acc[r][c], ah[r], bl[c], acc[r][c]);
                    wmma::mma_sync(acc[r][c], al[r], bh[c], acc[r][c]);
                }
        }

        // direct global stores (g_t1 padded -> no row guard needed)
        #pragma unroll
        for (int r = 0; r < 2; r++)
            #pragma unroll
            for (int c = 0; c < 2; c++)
                wmma::store_matrix_sync(T + (size_t)(row0 + m0 + r * 16) * 128 + n0 + c * 16,
                                        acc[r][c], 128, wmma::mem_row_major);
    }
}

// -------- finish layer1: gather t1 + mean + bias + sigmoid -> h (bf16 hi/lo) ----
__global__ void k_finish1(const float* __restrict__ T, const float* __restrict__ bias,
                          int n) {
    int gid = blockIdx.x * blockDim.x + threadIdx.x;     // node*16 + q
    int node = gid >> 4;
    int q = gid & 15;
    if (node >= n) return;
    int s = g_rowptr[node], e = g_rowptr[node + 1];
    float4 a0 = make_float4(0.f, 0.f, 0.f, 0.f);
    float4 a1 = make_float4(0.f, 0.f, 0.f, 0.f);
    int p = s;
    for (; p + 1 < e; p += 2) {
        int j0 = g_adj[p], j1 = g_adj[p + 1];
        float4 v0 = *(const float4*)(T + (size_t)j0 * 128 + q * 4);
        float4 v1 = *(const float4*)(T + (size_t)j1 * 128 + q * 4);
        a0.x += v0.x; a0.y += v0.y; a0.z += v0.z; a0.w += v0.w;
        a1.x += v1.x; a1.y += v1.y; a1.z += v1.z; a1.w += v1.w;
    }
    if (p < e) {
        int j = g_adj[p];
        float4 v = *(const float4*)(T + (size_t)j * 128 + q * 4);
        a0.x += v.x; a0.y += v.y; a0.z += v.z; a0.w += v.w;
    }
    a0.x += a1.x; a0.y += a1.y; a0.z += a1.z; a0.w += a1.w;
    float inv = 1.f / fmaxf((float)(e - s), 1.f);
    float4 r = *(const float4*)(T + (size_t)node * 128 + 64 + q * 4);
    float4 b = *(const float4*)(bias + q * 4);
    float4 o;
    o.x = fmaf(a0.x, inv, r.x + b.x);
    o.y = fmaf(a0.y, inv, r.y + b.y);
    o.z = fmaf(a0.z, inv, r.z + b.z);
    o.w = fmaf(a0.w, inv, r.w + b.w);
    o.x = 1.f / (1.f + expf(-o.x));
    o.y = 1.f / (1.f + expf(-o.y));
    o.z = 1.f / (1.f + expf(-o.z));
    o.w = 1.f / (1.f + expf(-o.w));
    uint32_t hi2[2], lo2[2];
    split4(o, hi2, lo2);
    *(uint2*)(g_hhi + (size_t)node * 64 + q * 4) = make_uint2(hi2[0], hi2[1]);
    *(uint2*)(g_hlo + (size_t)node * 64 + q * 4) = make_uint2(lo2[0], lo2[1]);
}

// ------------- GEMM2, persistent: T2 = H @ [W2l|W2r] (pre-split H) ------------
#define GEMM2_SMEM ((2 * 64 * PADB2 + 2 * 128 * PADA2) * 2)

__global__ void __launch_bounds__(320, 2)
k_gemm2_wmma(float* __restrict__ T, int n) {
    extern __shared__ char smraw[];
    __nv_bfloat16* Whi = (__nv_bfloat16*)smraw;           // [64][PADB2]
    __nv_bfloat16* Wlo = Whi + 64 * PADB2;
    __nv_bfloat16* Ahi = Wlo + 64 * PADB2;                // [128][PADA2]
    __nv_bfloat16* Alo = Ahi + 128 * PADA2;
    const int tid = threadIdx.x, wid = tid >> 5;

    for (int p = tid; p < 640; p += 320) {
        int k = p / 10, c = p % 10;
        *(uint4*)(Whi + k * PADB2 + c * 8) = ((const uint4*)g_w2hi)[p];
        *(uint4*)(Wlo + k * PADB2 + c * 8) = ((const uint4*)g_w2lo)[p];
    }

    const int n0 = (wid % 5) * 16;
    const int m0 = (wid / 5) * 64;
    const int ntiles = (n + 127) >> 7;

    for (int t = blockIdx.x; t < ntiles; t += gridDim.x) {
        const int row0 = t << 7;
        __syncthreads();
        for (int p = tid; p < 2048; p += 320) {
            int r = p >> 4, cq = p & 15;
            uint2 hv = make_uint2(0u, 0u), lv = make_uint2(0u, 0u);
            if (row0 + r < n) {
                hv = *(const uint2*)(g_hhi + (size_t)(row0 + r) * 64 + cq * 4);
                lv = *(const uint2*)(g_hlo + (size_t)(row0 + r) * 64 + cq * 4);
            }
            *(uint2*)(Ahi + r * PADA2 + cq * 4) = hv;
            *(uint2*)(Alo + r * PADA2 + cq * 4) = lv;
        }
        __syncthreads();

        wmma::fragment<wmma::accumulator, 16, 16, 16, float> acc[4];
        #pragma unroll
        for (int r = 0; r < 4; r++) wmma::fill_fragment(acc[r], 0.f);

        #pragma unroll
        for (int k = 0; k < 64; k += 16) {
            wmma::fragment<wmma::matrix_b, 16, 16, 16, __nv_bfloat16, wmma::row_major> bh, bl;
            wmma::load_matrix_sync(bh, Whi + k * PADB2 + n0, PADB2);
            wmma::load_matrix_sync(bl, Wlo + k * PADB2 + n0, PADB2);
            #pragma unroll
            for (int r = 0; r < 4; r++) {
                wmma::fragment<wmma::matrix_a, 16, 16, 16, __nv_bfloat16, wmma::row_major> ah, al;
                wmma::load_matrix_sync(ah, Ahi + (m0 + r * 16) * PADA2 + k, PADA2);
                wmma::load_matrix_sync(al, Alo + (m0 + r * 16) * PADA2 + k, PADA2);
                wmma::mma_sync(acc[r], ah, bh, acc[r]);
                wmma::mma_sync(acc[r], ah, bl, acc[r]);
                wmma::mma_sync(acc[r], al, bh, acc[r]);
            }
        }

        // direct global stores (g_t2 padded by 128 rows)
        #pragma unroll
        for (int r = 0; r < 4; r++)
            wmma::store_matrix_sync(T + (size_t)(row0 + m0 + r * 16) * 80 + n0,
                                    acc[r], 80, wmma::mem_row_major);
    }
}

// -------- final: aggregate t2 + mean + residual + bias --------
__global__ void k_finish2(const float* __restrict__ T, const float* __restrict__ bias,
                          float* __restrict__ out, int n) {
    constexpr int Q = 10;
    int gid = blockIdx.x * blockDim.x + threadIdx.x;
    int node = gid / Q;
    int q = gid - node * Q;
    if (node >= n) return;
    int s = g_rowptr[node], e = g_rowptr[node + 1];
    float4 a0 = make_float4(0.f, 0.f, 0.f, 0.f);
    float4 a1 = make_float4(0.f, 0.f, 0.f, 0.f);
    int p = s;
    for (; p + 1 < e; p += 2) {
        int j0 = g_adj[p], j1 = g_adj[p + 1];
        float4 v0 = *(const float4*)(T + (size_t)j0 * 80 + q * 4);
        float4 v1 = *(const float4*)(T + (size_t)j1 * 80 + q * 4);
        a0.x += v0.x; a0.y += v0.y; a0.z += v0.z; a0.w += v0.w;
        a1.x += v1.x; a1.y += v1.y; a1.z += v1.z; a1.w += v1.w;
    }
    if (p < e) {
        int j = g_adj[p];
        float4 v = *(const float4*)(T + (size_t)j * 80 + q * 4);
        a0.x += v.x; a0.y += v.y; a0.z += v.z; a0.w += v.w;
    }
    a0.x += a1.x; a0.y += a1.y; a0.z += a1.z; a0.w += a1.w;
    float inv = 1.f / fmaxf((float)(e - s), 1.f);
    float4 r = *(const float4*)(T + (size_t)node * 80 + 40 + q * 4);
    float4 b = *(const float4*)(bias + q * 4);
    float4 o;
    o.x = fmaf(a0.x, inv, r.x + b.x);
    o.y = fmaf(a0.y, inv, r.y + b.y);
    o.z = fmaf(a0.z, inv, r.z + b.z);
    o.w = fmaf(a0.w, inv, r.w + b.w);
    *(float4*)(out + (size_t)node * 40 + q * 4) = o;
    if (q == 0) g_cur[node] = 0;   // reset for next call
}

// ---------------- launch ----------------
extern "C" void kernel_launch(void* const* d_in, const int* in_sizes, int n_in,
                              void* d_out, int out_size) {
    const float* x   = (const float*)d_in[0];
    const void*  ei  = d_in[1];
    const float* W1l = (const float*)d_in[2];
    const float* b1  = (const float*)d_in[3];
    const float* W1r = (const float*)d_in[4];
    const float* W2l = (const float*)d_in[5];
    const float* b2  = (const float*)d_in[6];
    const float* W2r = (const float*)d_in[7];
    float* out = (float*)d_out;

    const int N = in_sizes[0] / NFEAT;
    const int E = in_sizes[1] / 2;
    const int NB = (N + SCAN_CHUNK - 1) / SCAN_CHUNK;
    const int EH = ((E + 1) / 2 + 255) / 256;

    void *t1p, *t2p;
    cudaGetSymbolAddress(&t1p, g_t1);
    cudaGetSymbolAddress(&t2p, g_t2);

    cudaFuncSetAttribute(k_gemm1_wmma, cudaFuncAttributeMaxDynamicSharedMemorySize, GEMM1_SMEM);
    cudaFuncSetAttribute(k_gemm2_wmma, cudaFuncAttributeMaxDynamicSharedMemorySize, GEMM2_SMEM);

    int g1 = 296;                          // 2 CTA/SM persistent
    if (g1 > (N + 63) / 64) g1 = (N + 63) / 64;
    int g2 = 296;
    if (g2 > (N + 127) / 128) g2 = (N + 127) / 128;

    // fork: side stream = weights + GEMM1; main stream = graph build
    cudaEventRecord(g_evFork, 0);
    cudaStreamWaitEvent(g_s2, g_evFork, 0);

    k_wsplit_all<<<21, 256, 0, g_s2>>>(W1l, W1r, W2l, W2r);          // #1
    k_hist<<<EH, 256>>>(ei, E, N);                                   // #2
    k_scan<<<NB, 1024>>>(N);                                         // #3
    k_gemm1_wmma<<<g1, 256, GEMM1_SMEM, g_s2>>>(x, (float*)t1p, N);  // #4
    k_fill<<<EH, 256>>>(ei, E, N);                                   // #5

    // join
    cudaEventRecord(g_evG1, g_s2);
    cudaStreamWaitEvent(0, g_evG1, 0);

    // tail
    int tot1 = N * 16;
    k_finish1<<<(tot1 + 255) / 256, 256>>>((const float*)t1p, b1, N);          // #6
    k_gemm2_wmma<<<g2, 320, GEMM2_SMEM>>>((float*)t2p, N);                     // #7
    int tot2 = N * 10;
    k_finish2<<<(tot2 + 255) / 256, 256>>>((const float*)t2p, b2, out, N);     // #8
}